// round 1
// baseline (speedup 1.0000x reference)
#include <cuda_runtime.h>
#include <math_constants.h>

// Problem constants (fixed by the reference):
//   outputs: (B, C) fp32, targets: (B,) i32, ages: (B,) i32, weight: (C,) fp32
//   T = 2.0 softmax temperature; output = scalar fp32 mean loss.
#define B_ROWS 32768
#define C_COLS 1024
#define ROWS_PER_BLOCK 8
#define NBLOCKS (B_ROWS / ROWS_PER_BLOCK) // 4096

// Scratch for deterministic two-stage reduction (no cudaMalloc allowed).
__device__ float g_partials[NBLOCKS];

// Stage 1: one warp per row. Row (1024 fp32 = 4 KB) fits in 32 regs/lane.
__global__ __launch_bounds__(ROWS_PER_BLOCK * 32)
void loss_rows_kernel(const float* __restrict__ outputs,
                      const int*   __restrict__ targets,
                      const int*   __restrict__ ages,
                      const float* __restrict__ weight) {
    const int warp = threadIdx.x >> 5;
    const int lane = threadIdx.x & 31;
    const int row  = blockIdx.x * ROWS_PER_BLOCK + warp;

    const float4* rp = reinterpret_cast<const float4*>(
        outputs + (size_t)row * C_COLS);

    // Load full row, coalesced: iteration k covers float4s [k*32 .. k*32+31].
    float4 v[8];
#pragma unroll
    for (int k = 0; k < 8; ++k) v[k] = rp[k * 32 + lane];

    // y = x / T  (T = 2.0)
    float m = -CUDART_INF_F;
#pragma unroll
    for (int k = 0; k < 8; ++k) {
        v[k].x *= 0.5f; v[k].y *= 0.5f; v[k].z *= 0.5f; v[k].w *= 0.5f;
        m = fmaxf(m, fmaxf(fmaxf(v[k].x, v[k].y), fmaxf(v[k].z, v[k].w)));
    }
#pragma unroll
    for (int off = 16; off > 0; off >>= 1)
        m = fmaxf(m, __shfl_xor_sync(0xFFFFFFFFu, m, off));

    float s = 0.0f;
#pragma unroll
    for (int k = 0; k < 8; ++k) {
        s += __expf(v[k].x - m);
        s += __expf(v[k].y - m);
        s += __expf(v[k].z - m);
        s += __expf(v[k].w - m);
    }
#pragma unroll
    for (int off = 16; off > 0; off >>= 1)
        s += __shfl_xor_sync(0xFFFFFFFFu, s, off);

    __shared__ float sh[ROWS_PER_BLOCK];
    if (lane == 0) {
        const float lse = m + __logf(s);
        const int   t    = targets[row];
        const float agef = (float)ages[row];
        const float delta = (agef > 50.0f && agef < 60.0f)
                                ? (agef - 50.0f) * 0.1f : 0.0f;
        // Re-reads of this row hit L1 (the warp just loaded those lines).
        const float yt  = outputs[(size_t)row * C_COLS + t]     * 0.5f;
        const float yt1 = outputs[(size_t)row * C_COLS + t + 1] * 0.5f;
        const float loss = -((1.0f - delta) * weight[t]     * (yt  - lse)
                           +         delta  * weight[t + 1] * (yt1 - lse));
        sh[warp] = loss;
    }
    __syncthreads();
    if (threadIdx.x == 0) {
        float p = 0.0f;
#pragma unroll
        for (int i = 0; i < ROWS_PER_BLOCK; ++i) p += sh[i];
        g_partials[blockIdx.x] = p;
    }
}

// Stage 2: single-block deterministic reduce of 4096 partials -> mean.
__global__ __launch_bounds__(1024)
void reduce_kernel(float* __restrict__ out) {
    const int tid  = threadIdx.x;
    const int lane = tid & 31;
    const int warp = tid >> 5;

    float s = 0.0f;
#pragma unroll
    for (int i = 0; i < NBLOCKS / 1024; ++i)
        s += g_partials[tid + i * 1024];

#pragma unroll
    for (int off = 16; off > 0; off >>= 1)
        s += __shfl_xor_sync(0xFFFFFFFFu, s, off);

    __shared__ float sh[32];
    if (lane == 0) sh[warp] = s;
    __syncthreads();
    if (warp == 0) {
        float t = sh[lane];
#pragma unroll
        for (int off = 16; off > 0; off >>= 1)
            t += __shfl_xor_sync(0xFFFFFFFFu, t, off);
        if (lane == 0) out[0] = t * (1.0f / (float)B_ROWS);
    }
}

extern "C" void kernel_launch(void* const* d_in, const int* in_sizes, int n_in,
                              void* d_out, int out_size) {
    const float* outputs = (const float*)d_in[0];
    const int*   targets = (const int*)d_in[1];
    const int*   ages    = (const int*)d_in[2];
    const float* weight  = (const float*)d_in[3];
    float*       out     = (float*)d_out;

    loss_rows_kernel<<<NBLOCKS, ROWS_PER_BLOCK * 32>>>(outputs, targets, ages, weight);
    reduce_kernel<<<1, 1024>>>(out);
}